// round 12
// baseline (speedup 1.0000x reference)
#include <cuda_runtime.h>

#define N_NODES 2048
#define F_IN    64
#define H_DIM   16
#define O_DIM   8
#define R_BLK   2

typedef unsigned long long ull;

// -------- scratch (no allocations allowed) --------
__device__ float g_fsums[N_NODES * O_DIM];

// ============================================================================
// packed f32x2 helpers (register-only asm; memory via typed C++ accesses)
// ============================================================================
__device__ __forceinline__ ull fma2(ull a, ull b, ull c) {
    ull d;
    asm("fma.rn.f32x2 %0, %1, %2, %3;" : "=l"(d) : "l"(a), "l"(b), "l"(c));
    return d;
}
__device__ __forceinline__ ull pack2(float v) {
    ull d;
    asm("mov.b64 %0, {%1, %1};" : "=l"(d) : "f"(v));
    return d;
}
__device__ __forceinline__ void unpack2(ull p, float& lo, float& hi) {
    asm("mov.b64 {%0, %1}, %2;" : "=f"(lo), "=f"(hi) : "l"(p));
}

// ============================================================================
// Kernel 1: k_fsum — grid=128, block=256, 16 nodes/block. (unchanged: proven)
// Per-block inline f-fold, then relu-split GEMV (exact for zero biases).
// ============================================================================
__global__ void __launch_bounds__(256)
k_fsum(const float* __restrict__ x,
       const float* __restrict__ fW1, const float* __restrict__ fb1,
       const float* __restrict__ fW2, const float* __restrict__ fb2,
       const float* __restrict__ fW3, const float* __restrict__ fb3)
{
    __shared__ float s_w1p[F_IN * H_DIM], s_w1n[F_IN * H_DIM];
    __shared__ float s_cp[F_IN * H_DIM],  s_cn[F_IN * H_DIM];
    __shared__ float s_A[F_IN * 16];

    const int tid = threadIdx.x;

    int nz = 0;
    for (int i = tid; i < F_IN * H_DIM; i += 256)
        nz |= (fb1[i] != 0.0f) | (fb2[i] != 0.0f);
    for (int i = tid; i < F_IN * O_DIM; i += 256)
        nz |= (fb3[i] != 0.0f);
    const int any_nz = __syncthreads_or(nz);

    const int node  = blockIdx.x * 16 + (tid >> 4);
    const int fbase = (tid & 15) * 4;

    float acc[O_DIM];
    #pragma unroll
    for (int o = 0; o < O_DIM; o++) acc[o] = 0.0f;

    if (!any_nz) {
        for (int i = tid; i < F_IN * H_DIM; i += 256) {
            const float w = fW1[i];
            s_w1p[i] = fmaxf(w, 0.0f);
            s_w1n[i] = fminf(w, 0.0f);
        }
        __syncthreads();

        {   // c pass
            const float4* W2 = (const float4*)fW2;
            #pragma unroll 4
            for (int k = 0; k < 16; k++) {
                const int idx = k * 256 + tid;
                const float4 v = __ldg(W2 + idx);
                const int f  = idx >> 6;
                const int hb = (idx & 3) * 4;
                const float* wp = s_w1p + f * H_DIM + hb;
                const float* wn = s_w1n + f * H_DIM + hb;
                float cp = v.x*wp[0] + v.y*wp[1] + v.z*wp[2] + v.w*wp[3];
                float cn = v.x*wn[0] + v.y*wn[1] + v.z*wn[2] + v.w*wn[3];
                cp += __shfl_xor_sync(0xFFFFFFFFu, cp, 1);
                cp += __shfl_xor_sync(0xFFFFFFFFu, cp, 2);
                cn += __shfl_xor_sync(0xFFFFFFFFu, cn, 1);
                cn += __shfl_xor_sync(0xFFFFFFFFu, cn, 2);
                if ((tid & 3) == 0) { s_cp[idx >> 2] = cp; s_cn[idx >> 2] = cn; }
            }
        }
        __syncthreads();

        {   // A pass
            const float4* W3 = (const float4*)fW3;
            #pragma unroll 4
            for (int k = 0; k < 8; k++) {
                const int j = k * 256 + tid;
                const float4 v = __ldg(W3 + j);
                const int f  = j >> 5;
                const int o  = (j >> 2) & 7;
                const int gb = (j & 3) * 4;
                const float* cpp = s_cp + f * H_DIM + gb;
                const float* cnn = s_cn + f * H_DIM + gb;
                float ap = v.x*fmaxf(cpp[0],0.f) + v.y*fmaxf(cpp[1],0.f)
                         + v.z*fmaxf(cpp[2],0.f) + v.w*fmaxf(cpp[3],0.f);
                float an = v.x*fminf(cnn[0],0.f) + v.y*fminf(cnn[1],0.f)
                         + v.z*fminf(cnn[2],0.f) + v.w*fminf(cnn[3],0.f);
                ap += __shfl_xor_sync(0xFFFFFFFFu, ap, 1);
                ap += __shfl_xor_sync(0xFFFFFFFFu, ap, 2);
                an += __shfl_xor_sync(0xFFFFFFFFu, an, 1);
                an += __shfl_xor_sync(0xFFFFFFFFu, an, 2);
                if ((tid & 3) == 0) {
                    s_A[f * 16 + o]     = ap;
                    s_A[f * 16 + 8 + o] = an;
                }
            }
        }
        __syncthreads();

        const float4 xv4 = __ldg((const float4*)(x + (size_t)node * F_IN + fbase));
        const float xv[4] = { xv4.x, xv4.y, xv4.z, xv4.w };
        #pragma unroll
        for (int ff = 0; ff < 4; ff++) {
            const int   f  = fbase + ff;
            const float xp = fmaxf(xv[ff], 0.0f);
            const float xn = fminf(xv[ff], 0.0f);
            #pragma unroll
            for (int o = 0; o < O_DIM; o++)
                acc[o] = fmaf(xp, s_A[f * 16 + o], fmaf(xn, s_A[f * 16 + 8 + o], acc[o]));
        }
    } else {
        for (int ff = 0; ff < 4; ff++) {
            const int   f  = fbase + ff;
            const float xv = x[(size_t)node * F_IN + f];
            float h1[H_DIM];
            #pragma unroll
            for (int k = 0; k < H_DIM; k++)
                h1[k] = fmaxf(fmaf(xv, __ldg(fW1 + f*H_DIM + k), __ldg(fb1 + f*H_DIM + k)), 0.0f);
            float h2[H_DIM];
            #pragma unroll
            for (int g = 0; g < H_DIM; g++) {
                float s = __ldg(fb2 + f*H_DIM + g);
                #pragma unroll
                for (int k = 0; k < H_DIM; k++)
                    s = fmaf(__ldg(fW2 + (f*H_DIM + g)*H_DIM + k), h1[k], s);
                h2[g] = fmaxf(s, 0.0f);
            }
            #pragma unroll
            for (int o = 0; o < O_DIM; o++) {
                float s = __ldg(fb3 + f*O_DIM + o);
                #pragma unroll
                for (int k = 0; k < H_DIM; k++)
                    s = fmaf(__ldg(fW3 + (f*O_DIM + o)*H_DIM + k), h2[k], s);
                acc[o] += s;
            }
        }
    }

    #pragma unroll
    for (int o = 0; o < O_DIM; o++) {
        acc[o] += __shfl_xor_sync(0xFFFFFFFFu, acc[o], 1);
        acc[o] += __shfl_xor_sync(0xFFFFFFFFu, acc[o], 2);
        acc[o] += __shfl_xor_sync(0xFFFFFFFFu, acc[o], 4);
        acc[o] += __shfl_xor_sync(0xFFFFFFFFu, acc[o], 8);
    }
    if ((tid & 15) == 0) {
        #pragma unroll
        for (int o = 0; o < O_DIM; o++)
            g_fsums[node * O_DIM + o] = acc[o];
    }
}

// ============================================================================
// Kernel 2: k_main — pred[i,:] = sum_j (m(d)/norm) * f_sums[j,:]
// R12: grid=1024, R_BLK=2, launch_bounds(256,3).
// Rationale: R9/R11 pinned at regs=128 (cap) with evidence of spill-inflated
// issue counts and occ 22%. Halving rows/block cuts acc 32->16 regs and d/n
// buffers 32->16 -> ~70 regs, comfortably under the 85-reg cap at 3 CTA/SM
// -> 24 warps/SM (+50%). Compute core unchanged (fma.rn.f32x2, swizzled
// smem fs table, no hot-loop shuffles).
// ============================================================================
__global__ void __launch_bounds__(256, 3)
k_main(const float* __restrict__ dmat, const float* __restrict__ nmat,
       const float* __restrict__ mW1, const float* __restrict__ mb1,
       const float* __restrict__ mW2, const float* __restrict__ mb2,
       const float* __restrict__ mW3, const float* __restrict__ mb3,
       float* __restrict__ out)
{
    __shared__ float4 s_fs[2048];        // 32KB fs half-table; reused for tail
    __shared__ float  s_p2[256];
    __shared__ float  s_ap, s_an, s_beta;
    __shared__ int    s_fast;
    __shared__ float  sw1[H_DIM], sb1v[H_DIM], sw2[H_DIM*H_DIM], sb2v[H_DIM], sw3[H_DIM];

    const int tid = threadIdx.x;
    const int i0  = blockIdx.x * R_BLK;

    // ---- warp 0: inline m-fold + zero-bias check ----
    if (tid < 32) {
        const int g = tid & 15;
        float cp = 0.0f, cn = 0.0f;
        #pragma unroll
        for (int h = 0; h < H_DIM; h++) {
            const float w2 = __ldg(mW2 + g * H_DIM + h);
            const float w1 = __ldg(mW1 + h);
            cp = fmaf(w2, fmaxf(w1, 0.0f), cp);
            cn = fmaf(w2, fminf(w1, 0.0f), cn);
        }
        const float w3 = __ldg(mW3 + g);
        float ap = (tid < 16) ? w3 * fmaxf(cp, 0.0f) : 0.0f;
        float an = (tid < 16) ? w3 * fminf(cn, 0.0f) : 0.0f;
        #pragma unroll
        for (int off = 16; off > 0; off >>= 1) {
            ap += __shfl_xor_sync(0xFFFFFFFFu, ap, off);
            an += __shfl_xor_sync(0xFFFFFFFFu, an, off);
        }
        int z = (__ldg(mb1 + g) == 0.0f) & (__ldg(mb2 + g) == 0.0f);
        z = __all_sync(0xFFFFFFFFu, z);
        if (tid == 0) { s_ap = ap; s_an = an; s_beta = __ldg(mb3); s_fast = z; }
    }
    __syncthreads();

    const int   mfast = s_fast;
    const float f_ap = s_ap, f_an = s_an, f_be = s_beta;

    ull acc[R_BLK][4];
    #pragma unroll
    for (int r = 0; r < R_BLK; r++)
        #pragma unroll
        for (int p = 0; p < 4; p++) acc[r][p] = 0ull;

    if (mfast) {
        #pragma unroll
        for (int t = 0; t < 2; t++) {
            const int j0 = t * 1024 + tid * 4;

            // d/n for this pass: 4 LDG.128, streaming
            float4 dv[R_BLK], nv[R_BLK];
            #pragma unroll
            for (int r = 0; r < R_BLK; r++) {
                dv[r] = __ldcs((const float4*)(dmat + (size_t)(i0 + r) * N_NODES + j0));
                nv[r] = __ldcs((const float4*)(nmat + (size_t)(i0 + r) * N_NODES + j0));
            }

            // stage 32KB fs half: coalesced LDG -> swizzled STS
            {
                const float4* src = (const float4*)g_fsums + t * 2048;
                #pragma unroll
                for (int q = 0; q < 8; q++) {
                    const int idx = q * 256 + tid;
                    const unsigned byte = (unsigned)idx * 16u;
                    s_fs[(byte ^ ((byte >> 3) & 0x70u)) >> 4] = __ldg(src + idx);
                }
            }
            __syncthreads();

            #pragma unroll
            for (int j = 0; j < 4; j++) {
                const unsigned byte0 = (unsigned)(tid * 4 + j) * 32u;
                const unsigned mask  = (byte0 >> 3) & 0x70u;
                const ulonglong2 pa = *(const ulonglong2*)((const char*)s_fs + (byte0 ^ mask));
                const ulonglong2 pb = *(const ulonglong2*)((const char*)s_fs + ((byte0 + 16u) ^ mask));

                #pragma unroll
                for (int r = 0; r < R_BLK; r++) {
                    const float d = (&dv[r].x)[j];
                    const float n = (&nv[r].x)[j];
                    const float m = fmaf(f_ap, fmaxf(d, 0.0f),
                                    fmaf(f_an, fminf(d, 0.0f), f_be));
                    const ull w2 = pack2(__fdividef(m, n));
                    acc[r][0] = fma2(w2, pa.x, acc[r][0]);
                    acc[r][1] = fma2(w2, pa.y, acc[r][1]);
                    acc[r][2] = fma2(w2, pb.x, acc[r][2]);
                    acc[r][3] = fma2(w2, pb.y, acc[r][3]);
                }
            }
            __syncthreads();           // before restage / tail reuse
        }
    } else {
        // ---- honest fallback: full per-pair m-MLP (never taken here) ----
        if (tid < H_DIM) {
            sw1[tid]  = mW1[tid]; sb1v[tid] = mb1[tid];
            sb2v[tid] = mb2[tid]; sw3[tid]  = mW3[tid];
        }
        sw2[tid] = mW2[tid];
        __syncthreads();
        const float b3v = mb3[0];

        for (int t = 0; t < 2; t++) {
            const int j0 = t * 1024 + tid * 4;
            float4 dv[R_BLK], nv[R_BLK];
            #pragma unroll
            for (int r = 0; r < R_BLK; r++) {
                dv[r] = __ldcs((const float4*)(dmat + (size_t)(i0 + r) * N_NODES + j0));
                nv[r] = __ldcs((const float4*)(nmat + (size_t)(i0 + r) * N_NODES + j0));
            }
            {
                const float4* src = (const float4*)g_fsums + t * 2048;
                #pragma unroll
                for (int q = 0; q < 8; q++) {
                    const int idx = q * 256 + tid;
                    const unsigned byte = (unsigned)idx * 16u;
                    s_fs[(byte ^ ((byte >> 3) & 0x70u)) >> 4] = __ldg(src + idx);
                }
            }
            __syncthreads();

            for (int j = 0; j < 4; j++) {
                const unsigned byte0 = (unsigned)(tid * 4 + j) * 32u;
                const unsigned mask  = (byte0 >> 3) & 0x70u;
                const ulonglong2 pa = *(const ulonglong2*)((const char*)s_fs + (byte0 ^ mask));
                const ulonglong2 pb = *(const ulonglong2*)((const char*)s_fs + ((byte0 + 16u) ^ mask));

                for (int r = 0; r < R_BLK; r++) {
                    const float d = (&dv[r].x)[j];
                    const float n = (&nv[r].x)[j];
                    float h1[H_DIM];
                    #pragma unroll
                    for (int k = 0; k < H_DIM; k++)
                        h1[k] = fmaxf(fmaf(d, sw1[k], sb1v[k]), 0.0f);
                    float m = b3v;
                    #pragma unroll
                    for (int g = 0; g < H_DIM; g++) {
                        float s = sb2v[g];
                        #pragma unroll
                        for (int k = 0; k < H_DIM; k++)
                            s = fmaf(sw2[g * H_DIM + k], h1[k], s);
                        m = fmaf(sw3[g], fmaxf(s, 0.0f), m);
                    }
                    const ull w2 = pack2(__fdividef(m, n));
                    acc[r][0] = fma2(w2, pa.x, acc[r][0]);
                    acc[r][1] = fma2(w2, pa.y, acc[r][1]);
                    acc[r][2] = fma2(w2, pb.x, acc[r][2]);
                    acc[r][3] = fma2(w2, pb.y, acc[r][3]);
                }
            }
            __syncthreads();
        }
    }

    // ---- tail: 16 partials/thread, 17-stride conflict-free smem reduction ----
    // stage A: s_red[tid*17 + idx] (bank = (tid*17+idx)%32; tid*17%32 bijective)
    float* s_red = (float*)s_fs;         // needs 256*17*4 = 17408B <= 32KB
    {
        #pragma unroll
        for (int r = 0; r < R_BLK; r++)
            #pragma unroll
            for (int p = 0; p < 4; p++) {
                float lo, hi;
                unpack2(acc[r][p], lo, hi);
                s_red[tid * 17 + r * 8 + 2 * p]     = lo;
                s_red[tid * 17 + r * 8 + 2 * p + 1] = hi;
            }
    }
    __syncthreads();

    // stage B: 16 reducers per value v (= r*8+o); k = tid>>4 sums 16 threads
    {
        const int v = tid & 15;
        const int k = tid >> 4;
        float s = 0.0f;
        #pragma unroll
        for (int m = 0; m < 16; m++)
            s += s_red[(k * 16 + m) * 17 + v];
        s_p2[k * 16 + v] = s;
    }
    __syncthreads();

    // stage C: 16 threads finish
    if (tid < 16) {
        float s = 0.0f;
        #pragma unroll
        for (int k = 0; k < 16; k++) s += s_p2[k * 16 + tid];
        out[i0 * O_DIM + tid] = s;       // tid = r*8+o (r in 0..1)
    }
}

// ============================================================================
// launch — 2 kernels
// ============================================================================
extern "C" void kernel_launch(void* const* d_in, const int* in_sizes, int n_in,
                              void* d_out, int out_size)
{
    const float* x   = (const float*)d_in[0];
    const float* dm  = (const float*)d_in[1];
    const float* nm  = (const float*)d_in[2];
    const float* fW1 = (const float*)d_in[3];
    const float* fb1 = (const float*)d_in[4];
    const float* fW2 = (const float*)d_in[5];
    const float* fb2 = (const float*)d_in[6];
    const float* fW3 = (const float*)d_in[7];
    const float* fb3 = (const float*)d_in[8];
    const float* mW1 = (const float*)d_in[9];
    const float* mb1 = (const float*)d_in[10];
    const float* mW2 = (const float*)d_in[11];
    const float* mb2 = (const float*)d_in[12];
    const float* mW3 = (const float*)d_in[13];
    const float* mb3 = (const float*)d_in[14];
    float* out = (float*)d_out;

    k_fsum<<<128, 256>>>(x, fW1, fb1, fW2, fb2, fW3, fb3);
    k_main<<<N_NODES / R_BLK, 256>>>(dm, nm, mW1, mb1, mW2, mb2, mW3, mb3, out);
}

// round 13
// speedup vs baseline: 1.1157x; 1.1157x over previous
#include <cuda_runtime.h>

#define N_NODES 2048
#define F_IN    64
#define H_DIM   16
#define O_DIM   8
#define R_BLK   4
#define NSTEP   8            // j-steps of 256

typedef unsigned long long ull;

// -------- scratch (no allocations allowed) --------
__device__ float g_fsums[N_NODES * O_DIM];

// ============================================================================
// packed f32x2 helpers (register-only asm; memory via typed C++ accesses)
// ============================================================================
__device__ __forceinline__ ull fma2(ull a, ull b, ull c) {
    ull d;
    asm("fma.rn.f32x2 %0, %1, %2, %3;" : "=l"(d) : "l"(a), "l"(b), "l"(c));
    return d;
}
__device__ __forceinline__ ull pack2(float v) {
    ull d;
    asm("mov.b64 %0, {%1, %1};" : "=l"(d) : "f"(v));
    return d;
}
__device__ __forceinline__ void unpack2(ull p, float& lo, float& hi) {
    asm("mov.b64 {%0, %1}, %2;" : "=f"(lo), "=f"(hi) : "l"(p));
}

// ============================================================================
// Kernel 1: k_fsum — grid=128, block=256, 16 nodes/block. (unchanged: proven)
// Per-block inline f-fold, then relu-split GEMV (exact for zero biases).
// ============================================================================
__global__ void __launch_bounds__(256)
k_fsum(const float* __restrict__ x,
       const float* __restrict__ fW1, const float* __restrict__ fb1,
       const float* __restrict__ fW2, const float* __restrict__ fb2,
       const float* __restrict__ fW3, const float* __restrict__ fb3)
{
    __shared__ float s_w1p[F_IN * H_DIM], s_w1n[F_IN * H_DIM];
    __shared__ float s_cp[F_IN * H_DIM],  s_cn[F_IN * H_DIM];
    __shared__ float s_A[F_IN * 16];

    const int tid = threadIdx.x;

    int nz = 0;
    for (int i = tid; i < F_IN * H_DIM; i += 256)
        nz |= (fb1[i] != 0.0f) | (fb2[i] != 0.0f);
    for (int i = tid; i < F_IN * O_DIM; i += 256)
        nz |= (fb3[i] != 0.0f);
    const int any_nz = __syncthreads_or(nz);

    const int node  = blockIdx.x * 16 + (tid >> 4);
    const int fbase = (tid & 15) * 4;

    float acc[O_DIM];
    #pragma unroll
    for (int o = 0; o < O_DIM; o++) acc[o] = 0.0f;

    if (!any_nz) {
        for (int i = tid; i < F_IN * H_DIM; i += 256) {
            const float w = fW1[i];
            s_w1p[i] = fmaxf(w, 0.0f);
            s_w1n[i] = fminf(w, 0.0f);
        }
        __syncthreads();

        {   // c pass
            const float4* W2 = (const float4*)fW2;
            #pragma unroll 4
            for (int k = 0; k < 16; k++) {
                const int idx = k * 256 + tid;
                const float4 v = __ldg(W2 + idx);
                const int f  = idx >> 6;
                const int hb = (idx & 3) * 4;
                const float* wp = s_w1p + f * H_DIM + hb;
                const float* wn = s_w1n + f * H_DIM + hb;
                float cp = v.x*wp[0] + v.y*wp[1] + v.z*wp[2] + v.w*wp[3];
                float cn = v.x*wn[0] + v.y*wn[1] + v.z*wn[2] + v.w*wn[3];
                cp += __shfl_xor_sync(0xFFFFFFFFu, cp, 1);
                cp += __shfl_xor_sync(0xFFFFFFFFu, cp, 2);
                cn += __shfl_xor_sync(0xFFFFFFFFu, cn, 1);
                cn += __shfl_xor_sync(0xFFFFFFFFu, cn, 2);
                if ((tid & 3) == 0) { s_cp[idx >> 2] = cp; s_cn[idx >> 2] = cn; }
            }
        }
        __syncthreads();

        {   // A pass
            const float4* W3 = (const float4*)fW3;
            #pragma unroll 4
            for (int k = 0; k < 8; k++) {
                const int j = k * 256 + tid;
                const float4 v = __ldg(W3 + j);
                const int f  = j >> 5;
                const int o  = (j >> 2) & 7;
                const int gb = (j & 3) * 4;
                const float* cpp = s_cp + f * H_DIM + gb;
                const float* cnn = s_cn + f * H_DIM + gb;
                float ap = v.x*fmaxf(cpp[0],0.f) + v.y*fmaxf(cpp[1],0.f)
                         + v.z*fmaxf(cpp[2],0.f) + v.w*fmaxf(cpp[3],0.f);
                float an = v.x*fminf(cnn[0],0.f) + v.y*fminf(cnn[1],0.f)
                         + v.z*fminf(cnn[2],0.f) + v.w*fminf(cnn[3],0.f);
                ap += __shfl_xor_sync(0xFFFFFFFFu, ap, 1);
                ap += __shfl_xor_sync(0xFFFFFFFFu, ap, 2);
                an += __shfl_xor_sync(0xFFFFFFFFu, an, 1);
                an += __shfl_xor_sync(0xFFFFFFFFu, an, 2);
                if ((tid & 3) == 0) {
                    s_A[f * 16 + o]     = ap;
                    s_A[f * 16 + 8 + o] = an;
                }
            }
        }
        __syncthreads();

        const float4 xv4 = __ldg((const float4*)(x + (size_t)node * F_IN + fbase));
        const float xv[4] = { xv4.x, xv4.y, xv4.z, xv4.w };
        #pragma unroll
        for (int ff = 0; ff < 4; ff++) {
            const int   f  = fbase + ff;
            const float xp = fmaxf(xv[ff], 0.0f);
            const float xn = fminf(xv[ff], 0.0f);
            #pragma unroll
            for (int o = 0; o < O_DIM; o++)
                acc[o] = fmaf(xp, s_A[f * 16 + o], fmaf(xn, s_A[f * 16 + 8 + o], acc[o]));
        }
    } else {
        for (int ff = 0; ff < 4; ff++) {
            const int   f  = fbase + ff;
            const float xv = x[(size_t)node * F_IN + f];
            float h1[H_DIM];
            #pragma unroll
            for (int k = 0; k < H_DIM; k++)
                h1[k] = fmaxf(fmaf(xv, __ldg(fW1 + f*H_DIM + k), __ldg(fb1 + f*H_DIM + k)), 0.0f);
            float h2[H_DIM];
            #pragma unroll
            for (int g = 0; g < H_DIM; g++) {
                float s = __ldg(fb2 + f*H_DIM + g);
                #pragma unroll
                for (int k = 0; k < H_DIM; k++)
                    s = fmaf(__ldg(fW2 + (f*H_DIM + g)*H_DIM + k), h1[k], s);
                h2[g] = fmaxf(s, 0.0f);
            }
            #pragma unroll
            for (int o = 0; o < O_DIM; o++) {
                float s = __ldg(fb3 + f*O_DIM + o);
                #pragma unroll
                for (int k = 0; k < H_DIM; k++)
                    s = fmaf(__ldg(fW3 + (f*O_DIM + o)*H_DIM + k), h2[k], s);
                acc[o] += s;
            }
        }
    }

    #pragma unroll
    for (int o = 0; o < O_DIM; o++) {
        acc[o] += __shfl_xor_sync(0xFFFFFFFFu, acc[o], 1);
        acc[o] += __shfl_xor_sync(0xFFFFFFFFu, acc[o], 2);
        acc[o] += __shfl_xor_sync(0xFFFFFFFFu, acc[o], 4);
        acc[o] += __shfl_xor_sync(0xFFFFFFFFu, acc[o], 8);
    }
    if ((tid & 15) == 0) {
        #pragma unroll
        for (int o = 0; o < O_DIM; o++)
            g_fsums[node * O_DIM + o] = acc[o];
    }
}

// ============================================================================
// Kernel 2: k_main — pred[i,:] = sum_j (m(d)/norm) * f_sums[j,:]
// R13: NO barriers / NO smem in the hot loop. Thread handles j = step*256+tid
// for 8 steps, R=4 rows:
//   - fs read directly: 2 LDG.128 per step, warp covers one contiguous 1KB
//     slice; 64KB table becomes L1-RESIDENT per SM (L1 persists across CTAs
//     within a launch) -> ~32cyc hits after warmup.
//   - d/n: perfectly coalesced per-lane LDG.32 streams (__ldcs).
//   - warps free-run (no lockstep stall windows — the R9-R12 limiter).
// grid=512, launch_bounds(256,3): ~75 regs -> 24 warps/SM.
// Tail: stride-33 conflict-free smem reduction (smem untouched until tail).
// ============================================================================
__global__ void __launch_bounds__(256, 3)
k_main(const float* __restrict__ dmat, const float* __restrict__ nmat,
       const float* __restrict__ mW1, const float* __restrict__ mb1,
       const float* __restrict__ mW2, const float* __restrict__ mb2,
       const float* __restrict__ mW3, const float* __restrict__ mb3,
       float* __restrict__ out)
{
    __shared__ float s_red[256 * 33];    // 33.8KB tail scratch
    __shared__ float s_p2[8 * 32];
    __shared__ float s_ap, s_an, s_beta;
    __shared__ int   s_fast;
    __shared__ float sw1[H_DIM], sb1v[H_DIM], sw2[H_DIM*H_DIM], sb2v[H_DIM], sw3[H_DIM];

    const int tid = threadIdx.x;
    const int i0  = blockIdx.x * R_BLK;

    // ---- warp 0: inline m-fold + zero-bias check ----
    if (tid < 32) {
        const int g = tid & 15;
        float cp = 0.0f, cn = 0.0f;
        #pragma unroll
        for (int h = 0; h < H_DIM; h++) {
            const float w2 = __ldg(mW2 + g * H_DIM + h);
            const float w1 = __ldg(mW1 + h);
            cp = fmaf(w2, fmaxf(w1, 0.0f), cp);
            cn = fmaf(w2, fminf(w1, 0.0f), cn);
        }
        const float w3 = __ldg(mW3 + g);
        float ap = (tid < 16) ? w3 * fmaxf(cp, 0.0f) : 0.0f;
        float an = (tid < 16) ? w3 * fminf(cn, 0.0f) : 0.0f;
        #pragma unroll
        for (int off = 16; off > 0; off >>= 1) {
            ap += __shfl_xor_sync(0xFFFFFFFFu, ap, off);
            an += __shfl_xor_sync(0xFFFFFFFFu, an, off);
        }
        int z = (__ldg(mb1 + g) == 0.0f) & (__ldg(mb2 + g) == 0.0f);
        z = __all_sync(0xFFFFFFFFu, z);
        if (tid == 0) { s_ap = ap; s_an = an; s_beta = __ldg(mb3); s_fast = z; }
    }
    __syncthreads();

    const int   mfast = s_fast;
    const float f_ap = s_ap, f_an = s_an, f_be = s_beta;

    ull acc[R_BLK][4];
    #pragma unroll
    for (int r = 0; r < R_BLK; r++)
        #pragma unroll
        for (int p = 0; p < 4; p++) acc[r][p] = 0ull;

    if (mfast) {
        #pragma unroll 2
        for (int step = 0; step < NSTEP; step++) {
            const int j = step * 256 + tid;

            // fs for this j: 2 LDG.128 (L1-resident table)
            const ulonglong2 pa = *(const ulonglong2*)(g_fsums + (size_t)j * O_DIM);
            const ulonglong2 pb = *(const ulonglong2*)(g_fsums + (size_t)j * O_DIM + 4);

            // d/n: coalesced per-lane LDG.32 streams
            float dv[R_BLK], nv[R_BLK];
            #pragma unroll
            for (int r = 0; r < R_BLK; r++) {
                dv[r] = __ldcs(dmat + (size_t)(i0 + r) * N_NODES + j);
                nv[r] = __ldcs(nmat + (size_t)(i0 + r) * N_NODES + j);
            }

            #pragma unroll
            for (int r = 0; r < R_BLK; r++) {
                const float m = fmaf(f_ap, fmaxf(dv[r], 0.0f),
                                fmaf(f_an, fminf(dv[r], 0.0f), f_be));
                const ull w2 = pack2(__fdividef(m, nv[r]));
                acc[r][0] = fma2(w2, pa.x, acc[r][0]);
                acc[r][1] = fma2(w2, pa.y, acc[r][1]);
                acc[r][2] = fma2(w2, pb.x, acc[r][2]);
                acc[r][3] = fma2(w2, pb.y, acc[r][3]);
            }
        }
    } else {
        // ---- honest fallback: full per-pair m-MLP (never taken here) ----
        if (tid < H_DIM) {
            sw1[tid]  = mW1[tid]; sb1v[tid] = mb1[tid];
            sb2v[tid] = mb2[tid]; sw3[tid]  = mW3[tid];
        }
        sw2[tid] = mW2[tid];
        __syncthreads();
        const float b3v = mb3[0];

        for (int step = 0; step < NSTEP; step++) {
            const int j = step * 256 + tid;
            const ulonglong2 pa = *(const ulonglong2*)(g_fsums + (size_t)j * O_DIM);
            const ulonglong2 pb = *(const ulonglong2*)(g_fsums + (size_t)j * O_DIM + 4);

            for (int r = 0; r < R_BLK; r++) {
                const float d = __ldcs(dmat + (size_t)(i0 + r) * N_NODES + j);
                const float n = __ldcs(nmat + (size_t)(i0 + r) * N_NODES + j);
                float h1[H_DIM];
                #pragma unroll
                for (int k = 0; k < H_DIM; k++)
                    h1[k] = fmaxf(fmaf(d, sw1[k], sb1v[k]), 0.0f);
                float m = b3v;
                #pragma unroll
                for (int g = 0; g < H_DIM; g++) {
                    float s = sb2v[g];
                    #pragma unroll
                    for (int k = 0; k < H_DIM; k++)
                        s = fmaf(sw2[g * H_DIM + k], h1[k], s);
                    m = fmaf(sw3[g], fmaxf(s, 0.0f), m);
                }
                const ull w2 = pack2(__fdividef(m, n));
                acc[r][0] = fma2(w2, pa.x, acc[r][0]);
                acc[r][1] = fma2(w2, pa.y, acc[r][1]);
                acc[r][2] = fma2(w2, pb.x, acc[r][2]);
                acc[r][3] = fma2(w2, pb.y, acc[r][3]);
            }
        }
    }

    // ---- tail: stride-33 conflict-free smem reduction ----
    // stage A: thread stores 32 partials at s_red[tid*33 + idx]
    //          (bank = (tid*33+idx)%32 = (tid+idx)%32 — conflict-free rows)
    {
        #pragma unroll
        for (int r = 0; r < R_BLK; r++)
            #pragma unroll
            for (int p = 0; p < 4; p++) {
                float lo, hi;
                unpack2(acc[r][p], lo, hi);
                s_red[tid * 33 + r * 8 + 2 * p]     = lo;
                s_red[tid * 33 + r * 8 + 2 * p + 1] = hi;
            }
    }
    __syncthreads();

    // stage B: 8 reducer groups; group k sums threads k*32..k*32+31 for value v
    {
        const int v = tid & 31;
        const int k = tid >> 5;
        float s = 0.0f;
        #pragma unroll
        for (int m = 0; m < 32; m++)
            s += s_red[(k * 32 + m) * 33 + v];
        s_p2[k * 32 + v] = s;
    }
    __syncthreads();

    // stage C: 32 threads finish (tid = r*8+o)
    if (tid < 32) {
        float s = 0.0f;
        #pragma unroll
        for (int k = 0; k < 8; k++) s += s_p2[k * 32 + tid];
        out[i0 * O_DIM + tid] = s;
    }
}

// ============================================================================
// launch — 2 kernels
// ============================================================================
extern "C" void kernel_launch(void* const* d_in, const int* in_sizes, int n_in,
                              void* d_out, int out_size)
{
    const float* x   = (const float*)d_in[0];
    const float* dm  = (const float*)d_in[1];
    const float* nm  = (const float*)d_in[2];
    const float* fW1 = (const float*)d_in[3];
    const float* fb1 = (const float*)d_in[4];
    const float* fW2 = (const float*)d_in[5];
    const float* fb2 = (const float*)d_in[6];
    const float* fW3 = (const float*)d_in[7];
    const float* fb3 = (const float*)d_in[8];
    const float* mW1 = (const float*)d_in[9];
    const float* mb1 = (const float*)d_in[10];
    const float* mW2 = (const float*)d_in[11];
    const float* mb2 = (const float*)d_in[12];
    const float* mW3 = (const float*)d_in[13];
    const float* mb3 = (const float*)d_in[14];
    float* out = (float*)d_out;

    k_fsum<<<128, 256>>>(x, fW1, fb1, fW2, fb2, fW3, fb3);
    k_main<<<N_NODES / R_BLK, 256>>>(dm, nm, mW1, mb1, mW2, mb2, mW3, mb3, out);
}

// round 16
// speedup vs baseline: 1.1900x; 1.0666x over previous
#include <cuda_runtime.h>

#define N_NODES 2048
#define F_IN    64
#define H_DIM   16
#define O_DIM   8
#define R_BLK   4

typedef unsigned long long ull;

// -------- scratch (no allocations allowed) --------
__device__ float g_fsums[N_NODES * O_DIM];

// ============================================================================
// packed f32x2 helpers (register-only asm; memory via typed C++ accesses)
// ============================================================================
__device__ __forceinline__ ull fma2(ull a, ull b, ull c) {
    ull d;
    asm("fma.rn.f32x2 %0, %1, %2, %3;" : "=l"(d) : "l"(a), "l"(b), "l"(c));
    return d;
}
__device__ __forceinline__ ull pack2(float v) {
    ull d;
    asm("mov.b64 %0, {%1, %1};" : "=l"(d) : "f"(v));
    return d;
}
__device__ __forceinline__ void unpack2(ull p, float& lo, float& hi) {
    asm("mov.b64 {%0, %1}, %2;" : "=f"(lo), "=f"(hi) : "l"(p));
}

// ============================================================================
// Kernel 1: k_fsum — grid=128, block=256, 16 nodes/block.
// Latency-window compression: x prefetched FIRST (DRAM read overlaps the
// whole fold), bias-check loads + W1 staging batched into ONE window closed
// by a single __syncthreads_or. Then c-pass (L2), A-pass (L2), GEMV.
// ============================================================================
__global__ void __launch_bounds__(256)
k_fsum(const float* __restrict__ x,
       const float* __restrict__ fW1, const float* __restrict__ fb1,
       const float* __restrict__ fW2, const float* __restrict__ fb2,
       const float* __restrict__ fW3, const float* __restrict__ fb3)
{
    __shared__ float s_w1p[F_IN * H_DIM], s_w1n[F_IN * H_DIM];
    __shared__ float s_cp[F_IN * H_DIM],  s_cn[F_IN * H_DIM];
    __shared__ float s_A[F_IN * 16];     // [f*16+o]=A+, [f*16+8+o]=A-

    const int tid   = threadIdx.x;
    const int node  = blockIdx.x * 16 + (tid >> 4);
    const int fbase = (tid & 15) * 4;

    // ---- prefetch x (longest latency) before everything else ----
    const float4 xv4 = __ldg((const float4*)(x + (size_t)node * F_IN + fbase));

    // ---- batched: bias checks + W1 stage, ONE window, ONE barrier ----
    int nz = 0;
    #pragma unroll
    for (int k = 0; k < 4; k++) {
        const int i = k * 256 + tid;
        nz |= (__ldg(fb1 + i) != 0.0f) | (__ldg(fb2 + i) != 0.0f);
        const float w = __ldg(fW1 + i);
        s_w1p[i] = fmaxf(w, 0.0f);
        s_w1n[i] = fminf(w, 0.0f);
    }
    #pragma unroll
    for (int k = 0; k < 2; k++)
        nz |= (__ldg(fb3 + k * 256 + tid) != 0.0f);
    const int any_nz = __syncthreads_or(nz);

    float acc[O_DIM];
    #pragma unroll
    for (int o = 0; o < O_DIM; o++) acc[o] = 0.0f;

    if (!any_nz) {
        {   // c pass: c±[f,g] = sum_h fW2[f,g,h]*w1±[f,h] (flat float4, L2)
            const float4* W2 = (const float4*)fW2;   // 4096 float4
            #pragma unroll 4
            for (int k = 0; k < 16; k++) {
                const int idx = k * 256 + tid;
                const float4 v = __ldg(W2 + idx);
                const int f  = idx >> 6;
                const int hb = (idx & 3) * 4;
                const float* wp = s_w1p + f * H_DIM + hb;
                const float* wn = s_w1n + f * H_DIM + hb;
                float cp = v.x*wp[0] + v.y*wp[1] + v.z*wp[2] + v.w*wp[3];
                float cn = v.x*wn[0] + v.y*wn[1] + v.z*wn[2] + v.w*wn[3];
                cp += __shfl_xor_sync(0xFFFFFFFFu, cp, 1);
                cp += __shfl_xor_sync(0xFFFFFFFFu, cp, 2);
                cn += __shfl_xor_sync(0xFFFFFFFFu, cn, 1);
                cn += __shfl_xor_sync(0xFFFFFFFFu, cn, 2);
                if ((tid & 3) == 0) { s_cp[idx >> 2] = cp; s_cn[idx >> 2] = cn; }
            }
        }
        __syncthreads();

        {   // A pass: A±[f,o] = sum_g fW3[f,o,g]*relu±(c±[f,g]) (L2)
            const float4* W3 = (const float4*)fW3;   // 2048 float4
            #pragma unroll 4
            for (int k = 0; k < 8; k++) {
                const int j = k * 256 + tid;
                const float4 v = __ldg(W3 + j);
                const int f  = j >> 5;
                const int o  = (j >> 2) & 7;
                const int gb = (j & 3) * 4;
                const float* cpp = s_cp + f * H_DIM + gb;
                const float* cnn = s_cn + f * H_DIM + gb;
                float ap = v.x*fmaxf(cpp[0],0.f) + v.y*fmaxf(cpp[1],0.f)
                         + v.z*fmaxf(cpp[2],0.f) + v.w*fmaxf(cpp[3],0.f);
                float an = v.x*fminf(cnn[0],0.f) + v.y*fminf(cnn[1],0.f)
                         + v.z*fminf(cnn[2],0.f) + v.w*fminf(cnn[3],0.f);
                ap += __shfl_xor_sync(0xFFFFFFFFu, ap, 1);
                ap += __shfl_xor_sync(0xFFFFFFFFu, ap, 2);
                an += __shfl_xor_sync(0xFFFFFFFFu, an, 1);
                an += __shfl_xor_sync(0xFFFFFFFFu, an, 2);
                if ((tid & 3) == 0) {
                    s_A[f * 16 + o]     = ap;
                    s_A[f * 16 + 8 + o] = an;
                }
            }
        }
        __syncthreads();

        // ---- relu-split GEMV with the prefetched x ----
        const float xv[4] = { xv4.x, xv4.y, xv4.z, xv4.w };
        #pragma unroll
        for (int ff = 0; ff < 4; ff++) {
            const int   f  = fbase + ff;
            const float xp = fmaxf(xv[ff], 0.0f);
            const float xn = fminf(xv[ff], 0.0f);
            #pragma unroll
            for (int o = 0; o < O_DIM; o++)
                acc[o] = fmaf(xp, s_A[f * 16 + o], fmaf(xn, s_A[f * 16 + 8 + o], acc[o]));
        }
    } else {
        // ---- honest fallback: full per-feature MLP chain (reuses xv4) ----
        const float xvv[4] = { xv4.x, xv4.y, xv4.z, xv4.w };
        for (int ff = 0; ff < 4; ff++) {
            const int   f  = fbase + ff;
            const float xv = xvv[ff];
            float h1[H_DIM];
            #pragma unroll
            for (int k = 0; k < H_DIM; k++)
                h1[k] = fmaxf(fmaf(xv, __ldg(fW1 + f*H_DIM + k), __ldg(fb1 + f*H_DIM + k)), 0.0f);
            float h2[H_DIM];
            #pragma unroll
            for (int g = 0; g < H_DIM; g++) {
                float s = __ldg(fb2 + f*H_DIM + g);
                #pragma unroll
                for (int k = 0; k < H_DIM; k++)
                    s = fmaf(__ldg(fW2 + (f*H_DIM + g)*H_DIM + k), h1[k], s);
                h2[g] = fmaxf(s, 0.0f);
            }
            #pragma unroll
            for (int o = 0; o < O_DIM; o++) {
                float s = __ldg(fb3 + f*O_DIM + o);
                #pragma unroll
                for (int k = 0; k < H_DIM; k++)
                    s = fmaf(__ldg(fW3 + (f*O_DIM + o)*H_DIM + k), h2[k], s);
                acc[o] += s;
            }
        }
    }

    // ---- reduce 16 feature-threads per node ----
    #pragma unroll
    for (int o = 0; o < O_DIM; o++) {
        acc[o] += __shfl_xor_sync(0xFFFFFFFFu, acc[o], 1);
        acc[o] += __shfl_xor_sync(0xFFFFFFFFu, acc[o], 2);
        acc[o] += __shfl_xor_sync(0xFFFFFFFFu, acc[o], 4);
        acc[o] += __shfl_xor_sync(0xFFFFFFFFu, acc[o], 8);
    }
    if ((tid & 15) == 0) {
        #pragma unroll
        for (int o = 0; o < O_DIM; o++)
            g_fsums[node * O_DIM + o] = acc[o];
    }
}

// ============================================================================
// Kernel 2: k_main — R9 VERBATIM (proven: ran at 16.6us in rounds 9 and 11).
// grid=512, block=256, R=4 rows, 2 passes of 1024 j.
//   - front-batch 8 LDG.128 of d/norm per pass
//   - 32KB f_sums half staged to SW128-swizzled smem, typed ulonglong2 loads
//   - O-dim accumulate with fma.rn.f32x2; tail = 2-stage smem reduction
// ============================================================================
__global__ void __launch_bounds__(256, 2)
k_main(const float* __restrict__ dmat, const float* __restrict__ nmat,
       const float* __restrict__ mW1, const float* __restrict__ mb1,
       const float* __restrict__ mW2, const float* __restrict__ mb2,
       const float* __restrict__ mW3, const float* __restrict__ mb3,
       float* __restrict__ out)
{
    __shared__ float4 s_fs[2048];        // 32KB: fs half-table, reused for tail
    __shared__ float  s_p2[8 * 32];
    __shared__ float  s_ap, s_an, s_beta;
    __shared__ int    s_fast;
    __shared__ float  sw1[H_DIM], sb1v[H_DIM], sw2[H_DIM*H_DIM], sb2v[H_DIM], sw3[H_DIM];

    const int tid = threadIdx.x;
    const int i0  = blockIdx.x * R_BLK;

    // ---- warp 0: inline m-fold + zero-bias check ----
    if (tid < 32) {
        const int g = tid & 15;
        float cp = 0.0f, cn = 0.0f;
        #pragma unroll
        for (int h = 0; h < H_DIM; h++) {
            const float w2 = __ldg(mW2 + g * H_DIM + h);
            const float w1 = __ldg(mW1 + h);
            cp = fmaf(w2, fmaxf(w1, 0.0f), cp);
            cn = fmaf(w2, fminf(w1, 0.0f), cn);
        }
        const float w3 = __ldg(mW3 + g);
        float ap = (tid < 16) ? w3 * fmaxf(cp, 0.0f) : 0.0f;
        float an = (tid < 16) ? w3 * fminf(cn, 0.0f) : 0.0f;
        #pragma unroll
        for (int off = 16; off > 0; off >>= 1) {
            ap += __shfl_xor_sync(0xFFFFFFFFu, ap, off);
            an += __shfl_xor_sync(0xFFFFFFFFu, an, off);
        }
        int z = (__ldg(mb1 + g) == 0.0f) & (__ldg(mb2 + g) == 0.0f);
        z = __all_sync(0xFFFFFFFFu, z);
        if (tid == 0) { s_ap = ap; s_an = an; s_beta = __ldg(mb3); s_fast = z; }
    }
    __syncthreads();

    const int   mfast = s_fast;
    const float f_ap = s_ap, f_an = s_an, f_be = s_beta;

    ull acc[R_BLK][4];
    #pragma unroll
    for (int r = 0; r < R_BLK; r++)
        #pragma unroll
        for (int p = 0; p < 4; p++) acc[r][p] = 0ull;

    if (mfast) {
        #pragma unroll
        for (int t = 0; t < 2; t++) {
            const int j0 = t * 1024 + tid * 4;

            // front-batch d/n (8 LDG.128, streaming)
            float4 dv[R_BLK], nv[R_BLK];
            #pragma unroll
            for (int r = 0; r < R_BLK; r++) {
                dv[r] = __ldcs((const float4*)(dmat + (size_t)(i0 + r) * N_NODES + j0));
                nv[r] = __ldcs((const float4*)(nmat + (size_t)(i0 + r) * N_NODES + j0));
            }

            // stage 32KB fs half: coalesced LDG -> swizzled STS
            {
                const float4* src = (const float4*)g_fsums + t * 2048;
                #pragma unroll
                for (int q = 0; q < 8; q++) {
                    const int idx = q * 256 + tid;
                    const unsigned byte = (unsigned)idx * 16u;
                    s_fs[(byte ^ ((byte >> 3) & 0x70u)) >> 4] = __ldg(src + idx);
                }
            }
            __syncthreads();

            #pragma unroll
            for (int j = 0; j < 4; j++) {
                const unsigned byte0 = (unsigned)(tid * 4 + j) * 32u;
                const unsigned mask  = (byte0 >> 3) & 0x70u;
                const ulonglong2 pa = *(const ulonglong2*)((const char*)s_fs + (byte0 ^ mask));
                const ulonglong2 pb = *(const ulonglong2*)((const char*)s_fs + ((byte0 + 16u) ^ mask));

                #pragma unroll
                for (int r = 0; r < R_BLK; r++) {
                    const float d = (&dv[r].x)[j];
                    const float n = (&nv[r].x)[j];
                    const float m = fmaf(f_ap, fmaxf(d, 0.0f),
                                    fmaf(f_an, fminf(d, 0.0f), f_be));
                    const ull w2 = pack2(__fdividef(m, n));
                    acc[r][0] = fma2(w2, pa.x, acc[r][0]);
                    acc[r][1] = fma2(w2, pa.y, acc[r][1]);
                    acc[r][2] = fma2(w2, pb.x, acc[r][2]);
                    acc[r][3] = fma2(w2, pb.y, acc[r][3]);
                }
            }
            __syncthreads();           // before restage / tail reuse
        }
    } else {
        // ---- honest fallback: full per-pair m-MLP (never taken here) ----
        if (tid < H_DIM) {
            sw1[tid]  = mW1[tid]; sb1v[tid] = mb1[tid];
            sb2v[tid] = mb2[tid]; sw3[tid]  = mW3[tid];
        }
        sw2[tid] = mW2[tid];
        __syncthreads();
        const float b3v = mb3[0];

        for (int t = 0; t < 2; t++) {
            const int j0 = t * 1024 + tid * 4;
            float4 dv[R_BLK], nv[R_BLK];
            #pragma unroll
            for (int r = 0; r < R_BLK; r++) {
                dv[r] = __ldcs((const float4*)(dmat + (size_t)(i0 + r) * N_NODES + j0));
                nv[r] = __ldcs((const float4*)(nmat + (size_t)(i0 + r) * N_NODES + j0));
            }
            {
                const float4* src = (const float4*)g_fsums + t * 2048;
                #pragma unroll
                for (int q = 0; q < 8; q++) {
                    const int idx = q * 256 + tid;
                    const unsigned byte = (unsigned)idx * 16u;
                    s_fs[(byte ^ ((byte >> 3) & 0x70u)) >> 4] = __ldg(src + idx);
                }
            }
            __syncthreads();

            for (int j = 0; j < 4; j++) {
                const unsigned byte0 = (unsigned)(tid * 4 + j) * 32u;
                const unsigned mask  = (byte0 >> 3) & 0x70u;
                const ulonglong2 pa = *(const ulonglong2*)((const char*)s_fs + (byte0 ^ mask));
                const ulonglong2 pb = *(const ulonglong2*)((const char*)s_fs + ((byte0 + 16u) ^ mask));

                for (int r = 0; r < R_BLK; r++) {
                    const float d = (&dv[r].x)[j];
                    const float n = (&nv[r].x)[j];
                    float h1[H_DIM];
                    #pragma unroll
                    for (int k = 0; k < H_DIM; k++)
                        h1[k] = fmaxf(fmaf(d, sw1[k], sb1v[k]), 0.0f);
                    float m = b3v;
                    #pragma unroll
                    for (int g = 0; g < H_DIM; g++) {
                        float s = sb2v[g];
                        #pragma unroll
                        for (int k = 0; k < H_DIM; k++)
                            s = fmaf(sw2[g * H_DIM + k], h1[k], s);
                        m = fmaf(sw3[g], fmaxf(s, 0.0f), m);
                    }
                    const ull w2 = pack2(__fdividef(m, n));
                    acc[r][0] = fma2(w2, pa.x, acc[r][0]);
                    acc[r][1] = fma2(w2, pa.y, acc[r][1]);
                    acc[r][2] = fma2(w2, pb.x, acc[r][2]);
                    acc[r][3] = fma2(w2, pb.y, acc[r][3]);
                }
            }
            __syncthreads();
        }
    }

    // ---- tail: 2-stage smem reduction over 256 threads, reusing s_fs ----
    float* s_red = (float*)s_fs;
    {
        float a[32];
        #pragma unroll
        for (int r = 0; r < R_BLK; r++)
            #pragma unroll
            for (int p = 0; p < 4; p++)
                unpack2(acc[r][p], a[r * 8 + 2 * p], a[r * 8 + 2 * p + 1]);

        #pragma unroll
        for (int q = 0; q < 8; q++) {
            const unsigned byte = (unsigned)tid * 128u + q * 16u;
            const unsigned swz  = byte ^ (((unsigned)tid & 7u) << 4);
            *(float4*)((char*)s_red + swz) =
                make_float4(a[q*4], a[q*4+1], a[q*4+2], a[q*4+3]);
        }
    }
    __syncthreads();

    {
        const int v = tid & 31;
        const int k = tid >> 5;
        float s = 0.0f;
        #pragma unroll
        for (int m = 0; m < 32; m++) {
            const unsigned M = (unsigned)(k * 32 + m);
            const unsigned byte = M * 128u + (unsigned)v * 4u;
            const unsigned swz  = byte ^ ((M & 7u) << 4);
            s += *(const float*)((const char*)s_red + swz);
        }
        s_p2[k * 32 + v] = s;
    }
    __syncthreads();
    if (tid < 32) {
        float s = 0.0f;
        #pragma unroll
        for (int k = 0; k < 8; k++) s += s_p2[k * 32 + tid];
        out[i0 * O_DIM + tid] = s;       // tid = r*8+o
    }
}

// ============================================================================
// launch — 2 kernels
// ============================================================================
extern "C" void kernel_launch(void* const* d_in, const int* in_sizes, int n_in,
                              void* d_out, int out_size)
{
    const float* x   = (const float*)d_in[0];
    const float* dm  = (const float*)d_in[1];
    const float* nm  = (const float*)d_in[2];
    const float* fW1 = (const float*)d_in[3];
    const float* fb1 = (const float*)d_in[4];
    const float* fW2 = (const float*)d_in[5];
    const float* fb2 = (const float*)d_in[6];
    const float* fW3 = (const float*)d_in[7];
    const float* fb3 = (const float*)d_in[8];
    const float* mW1 = (const float*)d_in[9];
    const float* mb1 = (const float*)d_in[10];
    const float* mW2 = (const float*)d_in[11];
    const float* mb2 = (const float*)d_in[12];
    const float* mW3 = (const float*)d_in[13];
    const float* mb3 = (const float*)d_in[14];
    float* out = (float*)d_out;

    k_fsum<<<128, 256>>>(x, fW1, fb1, fW2, fb2, fW3, fb3);
    k_main<<<N_NODES / R_BLK, 256>>>(dm, nm, mW1, mb1, mW2, mb2, mW3, mb3, out);
}

// round 17
// speedup vs baseline: 1.2170x; 1.0227x over previous
#include <cuda_runtime.h>

#define N_NODES 2048
#define F_IN    64
#define H_DIM   16
#define O_DIM   8
#define R_BLK   4

typedef unsigned long long ull;

// -------- scratch (no allocations allowed) --------
__device__ float g_fsums[N_NODES * O_DIM];

// ============================================================================
// packed f32x2 helpers (register-only asm; memory via typed C++ accesses)
// ============================================================================
__device__ __forceinline__ ull fma2(ull a, ull b, ull c) {
    ull d;
    asm("fma.rn.f32x2 %0, %1, %2, %3;" : "=l"(d) : "l"(a), "l"(b), "l"(c));
    return d;
}
__device__ __forceinline__ ull pack2(float v) {
    ull d;
    asm("mov.b64 %0, {%1, %1};" : "=l"(d) : "f"(v));
    return d;
}
__device__ __forceinline__ void unpack2(ull p, float& lo, float& hi) {
    asm("mov.b64 {%0, %1}, %2;" : "=f"(lo), "=f"(hi) : "l"(p));
}

// ============================================================================
// Kernel 1: k_fsum — grid=128, block=256, 16 nodes/block.
// R17: warp-autonomous fold — warp w, iteration k folds feature f = k*8+w
// entirely in-warp (c-phase 2 lanes/g, A-phase 4 lanes/o, shuffle reduces,
// per-warp smem c buffer, __syncwarp only). ONE block barrier total (the
// __syncthreads_or that also publishes s_A before the GEMV).
//   fx[o] = max(x,0)*A+[f,o] + min(x,0)*A-[f,o]   (exact for zero biases)
// Slow path: honest full per-feature MLP chain.
// ============================================================================
__global__ void __launch_bounds__(256)
k_fsum(const float* __restrict__ x,
       const float* __restrict__ fW1, const float* __restrict__ fb1,
       const float* __restrict__ fW2, const float* __restrict__ fb2,
       const float* __restrict__ fW3, const float* __restrict__ fb3)
{
    __shared__ float s_A[F_IN * 16];     // [f*16+o]=A+, [f*16+8+o]=A-
    __shared__ float s_cw[8][2][H_DIM];  // per-warp c buffer: [warp][p/n][g]

    const int tid   = threadIdx.x;
    const int warp  = tid >> 5;
    const int lane  = tid & 31;
    const int node  = blockIdx.x * 16 + (tid >> 4);
    const int fbase = (tid & 15) * 4;

    // ---- prefetch x (longest latency) before everything else ----
    const float4 xv4 = __ldg((const float4*)(x + (size_t)node * F_IN + fbase));

    // ---- bias checks (no barrier yet; folded into the single syncthreads_or)
    int nz = 0;
    #pragma unroll
    for (int k = 0; k < 4; k++) {
        const int i = k * 256 + tid;
        nz |= (__ldg(fb1 + i) != 0.0f) | (__ldg(fb2 + i) != 0.0f);
    }
    #pragma unroll
    for (int k = 0; k < 2; k++)
        nz |= (__ldg(fb3 + k * 256 + tid) != 0.0f);

    // ---- warp-autonomous fold: 8 iterations, feature f = k*8 + warp ----
    {
        const int gg = lane >> 1;        // c-phase: g index (0..15)
        const int hh = lane & 1;         //          h-half (0..1)
        const int oo = lane >> 2;        // A-phase: o index (0..7)
        const int qq = lane & 3;         //          g-quarter (0..3)

        #pragma unroll 2
        for (int k = 0; k < 8; k++) {
            const int f = k * 8 + warp;

            // c-phase: c±[g] = sum_h W2[f,g,h]*relu±(W1[f,h]); 2 lanes per g
            const float* w2row = fW2 + ((size_t)f * H_DIM + gg) * H_DIM + hh * 8;
            const float4 a0 = __ldg((const float4*)w2row);
            const float4 a1 = __ldg((const float4*)(w2row + 4));
            const float* w1row = fW1 + (size_t)f * H_DIM + hh * 8;
            const float4 b0 = __ldg((const float4*)w1row);
            const float4 b1 = __ldg((const float4*)(w1row + 4));

            float cp = a0.x * fmaxf(b0.x, 0.f) + a0.y * fmaxf(b0.y, 0.f)
                     + a0.z * fmaxf(b0.z, 0.f) + a0.w * fmaxf(b0.w, 0.f)
                     + a1.x * fmaxf(b1.x, 0.f) + a1.y * fmaxf(b1.y, 0.f)
                     + a1.z * fmaxf(b1.z, 0.f) + a1.w * fmaxf(b1.w, 0.f);
            float cn = a0.x * fminf(b0.x, 0.f) + a0.y * fminf(b0.y, 0.f)
                     + a0.z * fminf(b0.z, 0.f) + a0.w * fminf(b0.w, 0.f)
                     + a1.x * fminf(b1.x, 0.f) + a1.y * fminf(b1.y, 0.f)
                     + a1.z * fminf(b1.z, 0.f) + a1.w * fminf(b1.w, 0.f);
            cp += __shfl_xor_sync(0xFFFFFFFFu, cp, 1);   // combine h-halves
            cn += __shfl_xor_sync(0xFFFFFFFFu, cn, 1);
            if (hh == 0) {
                s_cw[warp][0][gg] = cp;
                s_cw[warp][1][gg] = cn;
            }
            __syncwarp();

            // A-phase: A±[o] = sum_g W3[f,o,g]*relu±(c±[g]); 4 lanes per o
            const float4 w3 = __ldg((const float4*)(fW3 + ((size_t)f * O_DIM + oo) * H_DIM + qq * 4));
            const float* cb = s_cw[warp][0] + qq * 4;
            const float* nb = s_cw[warp][1] + qq * 4;
            float ap = w3.x * fmaxf(cb[0], 0.f) + w3.y * fmaxf(cb[1], 0.f)
                     + w3.z * fmaxf(cb[2], 0.f) + w3.w * fmaxf(cb[3], 0.f);
            float an = w3.x * fminf(nb[0], 0.f) + w3.y * fminf(nb[1], 0.f)
                     + w3.z * fminf(nb[2], 0.f) + w3.w * fminf(nb[3], 0.f);
            ap += __shfl_xor_sync(0xFFFFFFFFu, ap, 1);
            ap += __shfl_xor_sync(0xFFFFFFFFu, ap, 2);
            an += __shfl_xor_sync(0xFFFFFFFFu, an, 1);
            an += __shfl_xor_sync(0xFFFFFFFFu, an, 2);
            if (qq == 0) {
                s_A[f * 16 + oo]     = ap;
                s_A[f * 16 + 8 + oo] = an;
            }
            __syncwarp();                // protect s_cw reuse next iteration
        }
    }

    // ---- the ONLY block barrier: bias verdict + publishes s_A ----
    const int any_nz = __syncthreads_or(nz);

    float acc[O_DIM];
    #pragma unroll
    for (int o = 0; o < O_DIM; o++) acc[o] = 0.0f;

    if (!any_nz) {
        // ---- relu-split GEMV with the prefetched x ----
        const float xv[4] = { xv4.x, xv4.y, xv4.z, xv4.w };
        #pragma unroll
        for (int ff = 0; ff < 4; ff++) {
            const int   f  = fbase + ff;
            const float xp = fmaxf(xv[ff], 0.0f);
            const float xn = fminf(xv[ff], 0.0f);
            #pragma unroll
            for (int o = 0; o < O_DIM; o++)
                acc[o] = fmaf(xp, s_A[f * 16 + o], fmaf(xn, s_A[f * 16 + 8 + o], acc[o]));
        }
    } else {
        // ---- honest fallback: full per-feature MLP chain (reuses xv4) ----
        const float xvv[4] = { xv4.x, xv4.y, xv4.z, xv4.w };
        for (int ff = 0; ff < 4; ff++) {
            const int   f  = fbase + ff;
            const float xv = xvv[ff];
            float h1[H_DIM];
            #pragma unroll
            for (int k = 0; k < H_DIM; k++)
                h1[k] = fmaxf(fmaf(xv, __ldg(fW1 + f*H_DIM + k), __ldg(fb1 + f*H_DIM + k)), 0.0f);
            float h2[H_DIM];
            #pragma unroll
            for (int g = 0; g < H_DIM; g++) {
                float s = __ldg(fb2 + f*H_DIM + g);
                #pragma unroll
                for (int k = 0; k < H_DIM; k++)
                    s = fmaf(__ldg(fW2 + (f*H_DIM + g)*H_DIM + k), h1[k], s);
                h2[g] = fmaxf(s, 0.0f);
            }
            #pragma unroll
            for (int o = 0; o < O_DIM; o++) {
                float s = __ldg(fb3 + f*O_DIM + o);
                #pragma unroll
                for (int k = 0; k < H_DIM; k++)
                    s = fmaf(__ldg(fW3 + (f*O_DIM + o)*H_DIM + k), h2[k], s);
                acc[o] += s;
            }
        }
    }

    // ---- reduce 16 feature-threads per node ----
    #pragma unroll
    for (int o = 0; o < O_DIM; o++) {
        acc[o] += __shfl_xor_sync(0xFFFFFFFFu, acc[o], 1);
        acc[o] += __shfl_xor_sync(0xFFFFFFFFu, acc[o], 2);
        acc[o] += __shfl_xor_sync(0xFFFFFFFFu, acc[o], 4);
        acc[o] += __shfl_xor_sync(0xFFFFFFFFu, acc[o], 8);
    }
    if ((tid & 15) == 0) {
        #pragma unroll
        for (int o = 0; o < O_DIM; o++)
            g_fsums[node * O_DIM + o] = acc[o];
    }
}

// ============================================================================
// Kernel 2: k_main — R9 VERBATIM (proven 16.2-16.6us across 4 runs).
// grid=512, block=256, R=4 rows, 2 passes of 1024 j.
// ============================================================================
__global__ void __launch_bounds__(256, 2)
k_main(const float* __restrict__ dmat, const float* __restrict__ nmat,
       const float* __restrict__ mW1, const float* __restrict__ mb1,
       const float* __restrict__ mW2, const float* __restrict__ mb2,
       const float* __restrict__ mW3, const float* __restrict__ mb3,
       float* __restrict__ out)
{
    __shared__ float4 s_fs[2048];        // 32KB: fs half-table, reused for tail
    __shared__ float  s_p2[8 * 32];
    __shared__ float  s_ap, s_an, s_beta;
    __shared__ int    s_fast;
    __shared__ float  sw1[H_DIM], sb1v[H_DIM], sw2[H_DIM*H_DIM], sb2v[H_DIM], sw3[H_DIM];

    const int tid = threadIdx.x;
    const int i0  = blockIdx.x * R_BLK;

    // ---- warp 0: inline m-fold + zero-bias check ----
    if (tid < 32) {
        const int g = tid & 15;
        float cp = 0.0f, cn = 0.0f;
        #pragma unroll
        for (int h = 0; h < H_DIM; h++) {
            const float w2 = __ldg(mW2 + g * H_DIM + h);
            const float w1 = __ldg(mW1 + h);
            cp = fmaf(w2, fmaxf(w1, 0.0f), cp);
            cn = fmaf(w2, fminf(w1, 0.0f), cn);
        }
        const float w3 = __ldg(mW3 + g);
        float ap = (tid < 16) ? w3 * fmaxf(cp, 0.0f) : 0.0f;
        float an = (tid < 16) ? w3 * fminf(cn, 0.0f) : 0.0f;
        #pragma unroll
        for (int off = 16; off > 0; off >>= 1) {
            ap += __shfl_xor_sync(0xFFFFFFFFu, ap, off);
            an += __shfl_xor_sync(0xFFFFFFFFu, an, off);
        }
        int z = (__ldg(mb1 + g) == 0.0f) & (__ldg(mb2 + g) == 0.0f);
        z = __all_sync(0xFFFFFFFFu, z);
        if (tid == 0) { s_ap = ap; s_an = an; s_beta = __ldg(mb3); s_fast = z; }
    }
    __syncthreads();

    const int   mfast = s_fast;
    const float f_ap = s_ap, f_an = s_an, f_be = s_beta;

    ull acc[R_BLK][4];
    #pragma unroll
    for (int r = 0; r < R_BLK; r++)
        #pragma unroll
        for (int p = 0; p < 4; p++) acc[r][p] = 0ull;

    if (mfast) {
        #pragma unroll
        for (int t = 0; t < 2; t++) {
            const int j0 = t * 1024 + tid * 4;

            // front-batch d/n (8 LDG.128, streaming)
            float4 dv[R_BLK], nv[R_BLK];
            #pragma unroll
            for (int r = 0; r < R_BLK; r++) {
                dv[r] = __ldcs((const float4*)(dmat + (size_t)(i0 + r) * N_NODES + j0));
                nv[r] = __ldcs((const float4*)(nmat + (size_t)(i0 + r) * N_NODES + j0));
            }

            // stage 32KB fs half: coalesced LDG -> swizzled STS
            {
                const float4* src = (const float4*)g_fsums + t * 2048;
                #pragma unroll
                for (int q = 0; q < 8; q++) {
                    const int idx = q * 256 + tid;
                    const unsigned byte = (unsigned)idx * 16u;
                    s_fs[(byte ^ ((byte >> 3) & 0x70u)) >> 4] = __ldg(src + idx);
                }
            }
            __syncthreads();

            #pragma unroll
            for (int j = 0; j < 4; j++) {
                const unsigned byte0 = (unsigned)(tid * 4 + j) * 32u;
                const unsigned mask  = (byte0 >> 3) & 0x70u;
                const ulonglong2 pa = *(const ulonglong2*)((const char*)s_fs + (byte0 ^ mask));
                const ulonglong2 pb = *(const ulonglong2*)((const char*)s_fs + ((byte0 + 16u) ^ mask));

                #pragma unroll
                for (int r = 0; r < R_BLK; r++) {
                    const float d = (&dv[r].x)[j];
                    const float n = (&nv[r].x)[j];
                    const float m = fmaf(f_ap, fmaxf(d, 0.0f),
                                    fmaf(f_an, fminf(d, 0.0f), f_be));
                    const ull w2 = pack2(__fdividef(m, n));
                    acc[r][0] = fma2(w2, pa.x, acc[r][0]);
                    acc[r][1] = fma2(w2, pa.y, acc[r][1]);
                    acc[r][2] = fma2(w2, pb.x, acc[r][2]);
                    acc[r][3] = fma2(w2, pb.y, acc[r][3]);
                }
            }
            __syncthreads();           // before restage / tail reuse
        }
    } else {
        // ---- honest fallback: full per-pair m-MLP (never taken here) ----
        if (tid < H_DIM) {
            sw1[tid]  = mW1[tid]; sb1v[tid] = mb1[tid];
            sb2v[tid] = mb2[tid]; sw3[tid]  = mW3[tid];
        }
        sw2[tid] = mW2[tid];
        __syncthreads();
        const float b3v = mb3[0];

        for (int t = 0; t < 2; t++) {
            const int j0 = t * 1024 + tid * 4;
            float4 dv[R_BLK], nv[R_BLK];
            #pragma unroll
            for (int r = 0; r < R_BLK; r++) {
                dv[r] = __ldcs((const float4*)(dmat + (size_t)(i0 + r) * N_NODES + j0));
                nv[r] = __ldcs((const float4*)(nmat + (size_t)(i0 + r) * N_NODES + j0));
            }
            {
                const float4* src = (const float4*)g_fsums + t * 2048;
                #pragma unroll
                for (int q = 0; q < 8; q++) {
                    const int idx = q * 256 + tid;
                    const unsigned byte = (unsigned)idx * 16u;
                    s_fs[(byte ^ ((byte >> 3) & 0x70u)) >> 4] = __ldg(src + idx);
                }
            }
            __syncthreads();

            for (int j = 0; j < 4; j++) {
                const unsigned byte0 = (unsigned)(tid * 4 + j) * 32u;
                const unsigned mask  = (byte0 >> 3) & 0x70u;
                const ulonglong2 pa = *(const ulonglong2*)((const char*)s_fs + (byte0 ^ mask));
                const ulonglong2 pb = *(const ulonglong2*)((const char*)s_fs + ((byte0 + 16u) ^ mask));

                for (int r = 0; r < R_BLK; r++) {
                    const float d = (&dv[r].x)[j];
                    const float n = (&nv[r].x)[j];
                    float h1[H_DIM];
                    #pragma unroll
                    for (int k = 0; k < H_DIM; k++)
                        h1[k] = fmaxf(fmaf(d, sw1[k], sb1v[k]), 0.0f);
                    float m = b3v;
                    #pragma unroll
                    for (int g = 0; g < H_DIM; g++) {
                        float s = sb2v[g];
                        #pragma unroll
                        for (int k = 0; k < H_DIM; k++)
                            s = fmaf(sw2[g * H_DIM + k], h1[k], s);
                        m = fmaf(sw3[g], fmaxf(s, 0.0f), m);
                    }
                    const ull w2 = pack2(__fdividef(m, n));
                    acc[r][0] = fma2(w2, pa.x, acc[r][0]);
                    acc[r][1] = fma2(w2, pa.y, acc[r][1]);
                    acc[r][2] = fma2(w2, pb.x, acc[r][2]);
                    acc[r][3] = fma2(w2, pb.y, acc[r][3]);
                }
            }
            __syncthreads();
        }
    }

    // ---- tail: 2-stage smem reduction over 256 threads, reusing s_fs ----
    float* s_red = (float*)s_fs;
    {
        float a[32];
        #pragma unroll
        for (int r = 0; r < R_BLK; r++)
            #pragma unroll
            for (int p = 0; p < 4; p++)
                unpack2(acc[r][p], a[r * 8 + 2 * p], a[r * 8 + 2 * p + 1]);

        #pragma unroll
        for (int q = 0; q < 8; q++) {
            const unsigned byte = (unsigned)tid * 128u + q * 16u;
            const unsigned swz  = byte ^ (((unsigned)tid & 7u) << 4);
            *(float4*)((char*)s_red + swz) =
                make_float4(a[q*4], a[q*4+1], a[q*4+2], a[q*4+3]);
        }
    }
    __syncthreads();

    {
        const int v = tid & 31;
        const int k = tid >> 5;
        float s = 0.0f;
        #pragma unroll
        for (int m = 0; m < 32; m++) {
            const unsigned M = (unsigned)(k * 32 + m);
            const unsigned byte = M * 128u + (unsigned)v * 4u;
            const unsigned swz  = byte ^ ((M & 7u) << 4);
            s += *(const float*)((const char*)s_red + swz);
        }
        s_p2[k * 32 + v] = s;
    }
    __syncthreads();
    if (tid < 32) {
        float s = 0.0f;
        #pragma unroll
        for (int k = 0; k < 8; k++) s += s_p2[k * 32 + tid];
        out[i0 * O_DIM + tid] = s;       // tid = r*8+o
    }
}

// ============================================================================
// launch — 2 kernels
// ============================================================================
extern "C" void kernel_launch(void* const* d_in, const int* in_sizes, int n_in,
                              void* d_out, int out_size)
{
    const float* x   = (const float*)d_in[0];
    const float* dm  = (const float*)d_in[1];
    const float* nm  = (const float*)d_in[2];
    const float* fW1 = (const float*)d_in[3];
    const float* fb1 = (const float*)d_in[4];
    const float* fW2 = (const float*)d_in[5];
    const float* fb2 = (const float*)d_in[6];
    const float* fW3 = (const float*)d_in[7];
    const float* fb3 = (const float*)d_in[8];
    const float* mW1 = (const float*)d_in[9];
    const float* mb1 = (const float*)d_in[10];
    const float* mW2 = (const float*)d_in[11];
    const float* mb2 = (const float*)d_in[12];
    const float* mW3 = (const float*)d_in[13];
    const float* mb3 = (const float*)d_in[14];
    float* out = (float*)d_out;

    k_fsum<<<128, 256>>>(x, fW1, fb1, fW2, fb2, fW3, fb3);
    k_main<<<N_NODES / R_BLK, 256>>>(dm, nm, mW1, mb1, mW2, mb2, mW3, mb3, out);
}